// round 4
// baseline (speedup 1.0000x reference)
#include <cuda_runtime.h>
#include <math.h>

typedef unsigned long long ull;

// Problem constants
#define T_DIM   1024
#define B_DIM   8
#define INDIM   512
#define NOUT    192          // 64 v + 64 k + 64 alpha
#define M_TOT   (T_DIM*B_DIM)   // 8192 rows (t,b)
#define NCH     128          // chunks for log-cumsum (chunk = 8 t)
#define TCHK    8            // t per chunk
#define NSEG    8            // segments for the S scan
#define SEGT    128          // t per segment

#define LOG_EPS (-18.420680743952367f)   // logf(1e-8f)

// ---------------- device scratch (no allocations allowed) ----------------
__device__ float g_Wt[INDIM*NOUT];     // transposed+concatenated weights [k][n]
__device__ float g_bias[NOUT];
__device__ float g_v [M_TOT*64];
__device__ float g_k [M_TOT*64];
__device__ float g_la[M_TOT*64];       // log(max(sigmoid(a),eps))
__device__ float g_kd[M_TOT*64];       // k * decay
__device__ float g_csum[NCH*512];      // per-chunk log sums
__device__ float g_carry[NCH*512];     // exclusive prefix of chunk sums
__device__ float g_inv[512];           // 1/(exp(total)+1e-8)
__device__ float g_P[(NSEG-1)*B_DIM*64*64];  // segment partial outer sums

// ---------------- packed fp32x2 helpers ----------------
__device__ __forceinline__ ull pk2(float a, float b){
    ull r;
    asm("mov.b64 %0, {%1,%2};" : "=l"(r) : "f"(a), "f"(b));
    return r;
}
__device__ __forceinline__ void fma2(ull &d, ull a, ull b){
    asm("fma.rn.f32x2 %0, %1, %2, %3;" : "=l"(d) : "l"(a), "l"(b), "l"(d));
}
__device__ __forceinline__ float2 up2(ull v){
    float lo, hi;
    asm("mov.b64 {%0,%1}, %2;" : "=f"(lo), "=f"(hi) : "l"(v));
    return make_float2(lo, hi);
}

// ---------------- K0: pack weights (transpose to [k][n]) + bias ----------------
__global__ void pack_weights(const float* __restrict__ Wv, const float* __restrict__ bv,
                             const float* __restrict__ Wk, const float* __restrict__ bk,
                             const float* __restrict__ Wa, const float* __restrict__ ba){
    int idx = blockIdx.x*256 + threadIdx.x;
    if (idx < NOUT*INDIM){
        int j = idx / INDIM;          // output col 0..191
        int k = idx - j*INDIM;        // k 0..511 (coalesced read)
        const float* W = (j < 64) ? Wv : ((j < 128) ? Wk : Wa);
        g_Wt[k*NOUT + j] = W[(j & 63)*INDIM + k];
    }
    if (idx < NOUT){
        g_bias[idx] = (idx < 64) ? bv[idx] : ((idx < 128) ? bk[idx-64] : ba[idx-128]);
    }
}

// ---------------- K1: projection GEMM (8192 x 512) x (512 x 192), packed f32x2 ----
// Block: 128 threads; tile 64 rows x 192 cols. Thread: 8 rows x 12 cols (6 pairs).
__global__ void __launch_bounds__(128) proj_kernel(const float* __restrict__ x){
    __shared__ float sW[16*192];   // 12 KB  (k-tile x all 192 n)
    __shared__ float sX[16*64];    // 4 KB   (k-tile x 64 m, transposed)
    __shared__ float sB[192];

    int tid = threadIdx.x;
    int tx = tid & 15;             // n-group: cols tx*12 .. tx*12+11
    int ty = tid >> 4;             // m-group: rows ty*8 .. ty*8+7  (0..7)
    for (int i = tid; i < 192; i += 128) sB[i] = g_bias[i];
    int mb = blockIdx.x * 64;

    ull acc[8][6];
    #pragma unroll
    for (int i = 0; i < 8; i++)
        #pragma unroll
        for (int p = 0; p < 6; p++) acc[i][p] = 0ull;

    for (int kk = 0; kk < INDIM; kk += 16){
        // W tile: 16*192 = 3072 floats = 768 float4 (6 per thread)
        {
            const float4* src = (const float4*)&g_Wt[kk*NOUT];
            float4* dst = (float4*)sW;
            #pragma unroll
            for (int i = 0; i < 6; i++) dst[tid + i*128] = src[tid + i*128];
        }
        // X tile, transposed: sX[k][m]; m = tid>>1 (0..63), kh = (tid&1)*8
        {
            int m  = tid >> 1;
            int kh = (tid & 1) * 8;
            #pragma unroll
            for (int q = 0; q < 2; q++){
                float4 xv = *(const float4*)&x[(mb + m)*INDIM + kk + kh + q*4];
                sX[(kh+q*4+0)*64 + m] = xv.x;
                sX[(kh+q*4+1)*64 + m] = xv.y;
                sX[(kh+q*4+2)*64 + m] = xv.z;
                sX[(kh+q*4+3)*64 + m] = xv.w;
            }
        }
        __syncthreads();
        #pragma unroll
        for (int k = 0; k < 16; k++){
            float4 xa = *(float4*)&sX[k*64 + ty*8];
            float4 xb = *(float4*)&sX[k*64 + ty*8 + 4];
            ull xp[8];
            xp[0] = pk2(xa.x, xa.x); xp[1] = pk2(xa.y, xa.y);
            xp[2] = pk2(xa.z, xa.z); xp[3] = pk2(xa.w, xa.w);
            xp[4] = pk2(xb.x, xb.x); xp[5] = pk2(xb.y, xb.y);
            xp[6] = pk2(xb.z, xb.z); xp[7] = pk2(xb.w, xb.w);
            ull w[6];
            #pragma unroll
            for (int p = 0; p < 6; p++)
                w[p] = *(ull*)&sW[k*192 + tx*12 + 2*p];
            #pragma unroll
            for (int mi = 0; mi < 8; mi++)
                #pragma unroll
                for (int p = 0; p < 6; p++)
                    fma2(acc[mi][p], xp[mi], w[p]);
        }
        __syncthreads();
    }

    // epilogue: bias + routing (v / k / fp32 stable log-sigmoid)
    #pragma unroll
    for (int mi = 0; mi < 8; mi++){
        int m = mb + ty*8 + mi;      // = t*8 + b
        #pragma unroll
        for (int p = 0; p < 6; p++){
            float2 av = up2(acc[mi][p]);
            #pragma unroll
            for (int q = 0; q < 2; q++){
                int n = tx*12 + 2*p + q;
                float val = ((q == 0) ? av.x : av.y) + sB[n];
                if (n < 64){
                    g_v[m*64 + n] = val;
                } else if (n < 128){
                    g_k[m*64 + (n - 64)] = val;
                } else {
                    // log(sigmoid(val)) = min(val,0) - log1p(exp(-|val|)), clamped
                    float lsig = fminf(val, 0.0f) - log1pf(expf(-fabsf(val)));
                    g_la[m*64 + (n - 128)] = fmaxf(lsig, LOG_EPS);
                }
            }
        }
    }
}

// ---------------- K2a: per-chunk log sums ----------------
__global__ void __launch_bounds__(512) chunk_logsum(){
    int c  = blockIdx.x;           // chunk 0..127
    int bn = threadIdx.x;          // (b*64+n) 0..511
    const float* p = g_la + c*TCHK*512 + bn;
    float s = 0.0f;
    #pragma unroll
    for (int i = 0; i < TCHK; i++) s += p[i*512];
    g_csum[c*512 + bn] = s;
}

// ---------------- K2p: exclusive prefix over chunks + inv denominator --------
__global__ void __launch_bounds__(512) carry_prefix(){
    int bn = threadIdx.x;
    float s = 0.0f;
    #pragma unroll 8
    for (int c = 0; c < NCH; c++){
        g_carry[c*512 + bn] = s;
        s += g_csum[c*512 + bn];
    }
    g_inv[bn] = 1.0f / (expf(s) + 1e-8f);   // ref: fp32 cumprod[-1] underflow -> 1e-8
}

// ---------------- K2b: decay + fold into k ----------------
__global__ void __launch_bounds__(512) decay_fold(){
    int c  = blockIdx.x;           // chunk 0..127
    int bn = threadIdx.x;
    float cum = g_carry[c*512 + bn];
    float inv = g_inv[bn];
    const float* lap = g_la + c*TCHK*512 + bn;
    const float* kp  = g_k  + c*TCHK*512 + bn;
    float*       kdp = g_kd + c*TCHK*512 + bn;
    #pragma unroll
    for (int i = 0; i < TCHK; i++){
        cum += lap[i*512];
        float dec = expf(cum) * inv;
        kdp[i*512] = kp[i*512] * dec;
    }
}

// ---------------- K4: segment partial outer sums ----------------
// grid (16 dq, 8 b, NSEG-1 seg), block 64 = (dg 0..3) x (nq 0..15)
__global__ void __launch_bounds__(64) seg_partial(){
    int dq = blockIdx.x, b = blockIdx.y, seg = blockIdx.z;
    __shared__ float s_v[SEGT*4];
    int tid = threadIdx.x;
    for (int i = tid; i < SEGT; i += 64){
        float4 vv = *(const float4*)&g_v[(seg*SEGT + i)*512 + b*64 + dq*4];
        *(float4*)&s_v[i*4] = vv;
    }
    __syncthreads();
    int dg = tid >> 4, nq = tid & 15;
    int d = dq*4 + dg;
    float4 acc = make_float4(0.f, 0.f, 0.f, 0.f);
    const float* kdp = g_kd + seg*SEGT*512 + b*64 + nq*4;
    #pragma unroll 8
    for (int t = 0; t < SEGT; t++){
        float4 kd = *(const float4*)(kdp + t*512);
        float vv = s_v[t*4 + dg];
        acc.x = fmaf(vv, kd.x, acc.x);
        acc.y = fmaf(vv, kd.y, acc.y);
        acc.z = fmaf(vv, kd.z, acc.z);
        acc.w = fmaf(vv, kd.w, acc.w);
    }
    *(float4*)&g_P[(seg*B_DIM + b)*4096 + d*64 + nq*4] = acc;
}

// ---------------- K5: segmented scan + store (128 MB) ----------------
// grid (16 dq, 8 b, NSEG seg), block 64 = (dg 0..3) x (nq 0..15)
__global__ void __launch_bounds__(64) scan_kernel(float* __restrict__ out){
    int dq = blockIdx.x, b = blockIdx.y, seg = blockIdx.z;
    __shared__ float s_v[SEGT*4];
    int tid = threadIdx.x;
    for (int i = tid; i < SEGT; i += 64){
        float4 vv = *(const float4*)&g_v[(seg*SEGT + i)*512 + b*64 + dq*4];
        *(float4*)&s_v[i*4] = vv;
    }
    __syncthreads();
    int dg = tid >> 4, nq = tid & 15;
    int d = dq*4 + dg;
    float4 acc = make_float4(0.f, 0.f, 0.f, 0.f);
    for (int s = 0; s < seg; s++){
        float4 pv = *(const float4*)&g_P[(s*B_DIM + b)*4096 + d*64 + nq*4];
        acc.x += pv.x; acc.y += pv.y; acc.z += pv.z; acc.w += pv.w;
    }
    const float* kdp = g_kd + seg*SEGT*512 + b*64 + nq*4;
    float* outp = out + (size_t)(seg*SEGT)*32768 + b*4096 + d*64 + nq*4;
    #pragma unroll 8
    for (int t = 0; t < SEGT; t++){
        float4 kd = *(const float4*)(kdp + t*512);
        float vv = s_v[t*4 + dg];
        acc.x = fmaf(vv, kd.x, acc.x);
        acc.y = fmaf(vv, kd.y, acc.y);
        acc.z = fmaf(vv, kd.z, acc.z);
        acc.w = fmaf(vv, kd.w, acc.w);
        *(float4*)(outp + (size_t)t*32768) = acc;
    }
}

// ---------------- launch ----------------
extern "C" void kernel_launch(void* const* d_in, const int* in_sizes, int n_in,
                              void* d_out, int out_size){
    const float* x  = (const float*)d_in[0];
    const float* Wv = (const float*)d_in[1];
    const float* bv = (const float*)d_in[2];
    const float* Wk = (const float*)d_in[3];
    const float* bk = (const float*)d_in[4];
    const float* Wa = (const float*)d_in[5];
    const float* ba = (const float*)d_in[6];
    float* out = (float*)d_out;

    pack_weights<<<(NOUT*INDIM + 255)/256, 256>>>(Wv, bv, Wk, bk, Wa, ba);
    proj_kernel<<<M_TOT/64, 128>>>(x);
    chunk_logsum<<<NCH, 512>>>();
    carry_prefix<<<1, 512>>>();
    decay_fold<<<NCH, 512>>>();
    dim3 g4(16, B_DIM, NSEG-1);
    seg_partial<<<g4, 64>>>();
    dim3 g5(16, B_DIM, NSEG);
    scan_kernel<<<g5, 64>>>(out);
}

// round 5
// speedup vs baseline: 1.1648x; 1.1648x over previous
#include <cuda_runtime.h>
#include <math.h>

typedef unsigned long long ull;

// Problem constants
#define T_DIM   1024
#define B_DIM   8
#define INDIM   512
#define NOUT    192          // 64 v + 64 k + 64 alpha
#define M_TOT   (T_DIM*B_DIM)   // 8192 rows (t,b)
#define NCH     128          // chunks for log-cumsum (chunk = 8 t)
#define TCHK    8            // t per chunk
#define NSEG    8            // segments for the S scan
#define SEGT    128          // t per segment

#define LOG_EPS (-18.420680743952367f)   // logf(1e-8f)

// ---------------- device scratch (no allocations allowed) ----------------
__device__ float g_Wt[INDIM*NOUT];     // transposed+concatenated weights [k][n]
__device__ float g_bias[NOUT];
__device__ float g_v [M_TOT*64];
__device__ float g_k [M_TOT*64];
__device__ float g_la[M_TOT*64];       // log(max(sigmoid(a),eps))
__device__ float g_kd[M_TOT*64];       // k * decay
__device__ float g_csum[NCH*512];      // per-chunk log sums
__device__ float g_carry[NCH*512];     // exclusive prefix of chunk sums
__device__ float g_inv[512];           // 1/(exp(total)+1e-8)
__device__ float g_P[(NSEG-1)*B_DIM*64*64];  // segment partial outer sums

// ---------------- packed fp32x2 helpers ----------------
__device__ __forceinline__ ull pk2(float a, float b){
    ull r;
    asm("mov.b64 %0, {%1,%2};" : "=l"(r) : "f"(a), "f"(b));
    return r;
}
__device__ __forceinline__ void fma2(ull &d, ull a, ull b){
    asm("fma.rn.f32x2 %0, %1, %2, %3;" : "=l"(d) : "l"(a), "l"(b), "l"(d));
}
__device__ __forceinline__ float2 up2(ull v){
    float lo, hi;
    asm("mov.b64 {%0,%1}, %2;" : "=f"(lo), "=f"(hi) : "l"(v));
    return make_float2(lo, hi);
}

// ---------------- K0: pack weights (transpose to [k][n]) + bias ----------------
__global__ void pack_weights(const float* __restrict__ Wv, const float* __restrict__ bv,
                             const float* __restrict__ Wk, const float* __restrict__ bk,
                             const float* __restrict__ Wa, const float* __restrict__ ba){
    int idx = blockIdx.x*256 + threadIdx.x;
    if (idx < NOUT*INDIM){
        int j = idx / INDIM;          // output col 0..191
        int k = idx - j*INDIM;        // k 0..511 (coalesced read)
        const float* W = (j < 64) ? Wv : ((j < 128) ? Wk : Wa);
        g_Wt[k*NOUT + j] = W[(j & 63)*INDIM + k];
    }
    if (idx < NOUT){
        g_bias[idx] = (idx < 64) ? bv[idx] : ((idx < 128) ? bk[idx-64] : ba[idx-128]);
    }
}

// ---------------- K1: projection GEMM (8192 x 512) x (512 x 192), packed f32x2 ----
// Block: 128 threads; tile 64 rows x 192 cols. Thread: 8 rows x 12 cols (6 pairs).
__global__ void __launch_bounds__(128) proj_kernel(const float* __restrict__ x){
    __shared__ float sW[16*192];   // 12 KB  (k-tile x all 192 n)
    __shared__ float sX[16*64];    // 4 KB   (k-tile x 64 m, transposed)
    __shared__ float sB[192];

    int tid = threadIdx.x;
    int tx = tid & 15;             // n-group: cols tx*12 .. tx*12+11
    int ty = tid >> 4;             // m-group: rows ty*8 .. ty*8+7  (0..7)
    for (int i = tid; i < 192; i += 128) sB[i] = g_bias[i];
    int mb = blockIdx.x * 64;

    ull acc[8][6];
    #pragma unroll
    for (int i = 0; i < 8; i++)
        #pragma unroll
        for (int p = 0; p < 6; p++) acc[i][p] = 0ull;

    for (int kk = 0; kk < INDIM; kk += 16){
        // W tile: 16*192 = 3072 floats = 768 float4 (6 per thread)
        {
            const float4* src = (const float4*)&g_Wt[kk*NOUT];
            float4* dst = (float4*)sW;
            #pragma unroll
            for (int i = 0; i < 6; i++) dst[tid + i*128] = src[tid + i*128];
        }
        // X tile, transposed: sX[k][m]; m = tid>>1 (0..63), kh = (tid&1)*8
        {
            int m  = tid >> 1;
            int kh = (tid & 1) * 8;
            #pragma unroll
            for (int q = 0; q < 2; q++){
                float4 xv = *(const float4*)&x[(mb + m)*INDIM + kk + kh + q*4];
                sX[(kh+q*4+0)*64 + m] = xv.x;
                sX[(kh+q*4+1)*64 + m] = xv.y;
                sX[(kh+q*4+2)*64 + m] = xv.z;
                sX[(kh+q*4+3)*64 + m] = xv.w;
            }
        }
        __syncthreads();
        #pragma unroll
        for (int k = 0; k < 16; k++){
            float4 xa = *(float4*)&sX[k*64 + ty*8];
            float4 xb = *(float4*)&sX[k*64 + ty*8 + 4];
            ull xp[8];
            xp[0] = pk2(xa.x, xa.x); xp[1] = pk2(xa.y, xa.y);
            xp[2] = pk2(xa.z, xa.z); xp[3] = pk2(xa.w, xa.w);
            xp[4] = pk2(xb.x, xb.x); xp[5] = pk2(xb.y, xb.y);
            xp[6] = pk2(xb.z, xb.z); xp[7] = pk2(xb.w, xb.w);
            ull w[6];
            #pragma unroll
            for (int p = 0; p < 6; p++)
                w[p] = *(ull*)&sW[k*192 + tx*12 + 2*p];
            #pragma unroll
            for (int mi = 0; mi < 8; mi++)
                #pragma unroll
                for (int p = 0; p < 6; p++)
                    fma2(acc[mi][p], xp[mi], w[p]);
        }
        __syncthreads();
    }

    // epilogue: bias + routing (v / k / fp32 stable log-sigmoid)
    #pragma unroll
    for (int mi = 0; mi < 8; mi++){
        int m = mb + ty*8 + mi;      // = t*8 + b
        #pragma unroll
        for (int p = 0; p < 6; p++){
            float2 av = up2(acc[mi][p]);
            #pragma unroll
            for (int q = 0; q < 2; q++){
                int n = tx*12 + 2*p + q;
                float val = ((q == 0) ? av.x : av.y) + sB[n];
                if (n < 64){
                    g_v[m*64 + n] = val;
                } else if (n < 128){
                    g_k[m*64 + (n - 64)] = val;
                } else {
                    // log(sigmoid(val)) = min(val,0) - log1p(exp(-|val|)), clamped
                    float lsig = fminf(val, 0.0f) - log1pf(expf(-fabsf(val)));
                    g_la[m*64 + (n - 128)] = fmaxf(lsig, LOG_EPS);
                }
            }
        }
    }
}

// ---------------- K2a: per-chunk log sums ----------------
__global__ void __launch_bounds__(512) chunk_logsum(){
    int c  = blockIdx.x;           // chunk 0..127
    int bn = threadIdx.x;          // (b*64+n) 0..511
    const float* p = g_la + c*TCHK*512 + bn;
    float s = 0.0f;
    #pragma unroll
    for (int i = 0; i < TCHK; i++) s += p[i*512];
    g_csum[c*512 + bn] = s;
}

// ---------------- K2p: warp-per-bn exclusive prefix over chunks ----------------
// 512 warps total: grid 16 x 1024 threads. Each warp scans its bn's 128 chunks
// in 4 shuffle passes. Exclusive value comes from shfl_up shift (exact assoc).
__global__ void __launch_bounds__(1024) carry_prefix(){
    int lane = threadIdx.x & 31;
    int bn   = (blockIdx.x * 1024 + threadIdx.x) >> 5;   // 0..511
    float carry = 0.0f;
    #pragma unroll
    for (int pass = 0; pass < 4; pass++){
        int c = pass*32 + lane;
        float v = g_csum[c*512 + bn];
        // inclusive warp scan
        float s = v;
        #pragma unroll
        for (int off = 1; off < 32; off <<= 1){
            float t = __shfl_up_sync(0xffffffffu, s, off);
            if (lane >= off) s += t;
        }
        // exclusive = previous lane's inclusive (lane 0 -> 0)
        float ex = __shfl_up_sync(0xffffffffu, s, 1);
        if (lane == 0) ex = 0.0f;
        g_carry[c*512 + bn] = carry + ex;
        carry += __shfl_sync(0xffffffffu, s, 31);
    }
    if (lane == 31) g_inv[bn] = 1.0f / (expf(carry) + 1e-8f);  // ref underflow -> 1e-8
}

// ---------------- K2b: decay + fold into k ----------------
__global__ void __launch_bounds__(512) decay_fold(){
    int c  = blockIdx.x;           // chunk 0..127
    int bn = threadIdx.x;
    float cum = g_carry[c*512 + bn];
    float inv = g_inv[bn];
    const float* lap = g_la + c*TCHK*512 + bn;
    const float* kp  = g_k  + c*TCHK*512 + bn;
    float*       kdp = g_kd + c*TCHK*512 + bn;
    #pragma unroll
    for (int i = 0; i < TCHK; i++){
        cum += lap[i*512];
        float dec = expf(cum) * inv;
        kdp[i*512] = kp[i*512] * dec;
    }
}

// ---------------- K4: segment partial outer sums ----------------
// grid (16 dq, 8 b, NSEG-1 seg), block 64 = (dg 0..3) x (nq 0..15)
__global__ void __launch_bounds__(64) seg_partial(){
    int dq = blockIdx.x, b = blockIdx.y, seg = blockIdx.z;
    __shared__ float s_v[SEGT*4];
    int tid = threadIdx.x;
    for (int i = tid; i < SEGT; i += 64){
        float4 vv = *(const float4*)&g_v[(seg*SEGT + i)*512 + b*64 + dq*4];
        *(float4*)&s_v[i*4] = vv;
    }
    __syncthreads();
    int dg = tid >> 4, nq = tid & 15;
    int d = dq*4 + dg;
    float4 acc = make_float4(0.f, 0.f, 0.f, 0.f);
    const float* kdp = g_kd + seg*SEGT*512 + b*64 + nq*4;
    #pragma unroll 8
    for (int t = 0; t < SEGT; t++){
        float4 kd = *(const float4*)(kdp + t*512);
        float vv = s_v[t*4 + dg];
        acc.x = fmaf(vv, kd.x, acc.x);
        acc.y = fmaf(vv, kd.y, acc.y);
        acc.z = fmaf(vv, kd.z, acc.z);
        acc.w = fmaf(vv, kd.w, acc.w);
    }
    *(float4*)&g_P[(seg*B_DIM + b)*4096 + d*64 + nq*4] = acc;
}

// ---------------- K5: segmented scan + store (128 MB) ----------------
// grid (16 dq, 8 b, NSEG seg), block 64 = (dg 0..3) x (nq 0..15)
__global__ void __launch_bounds__(64) scan_kernel(float* __restrict__ out){
    int dq = blockIdx.x, b = blockIdx.y, seg = blockIdx.z;
    __shared__ float s_v[SEGT*4];
    int tid = threadIdx.x;
    for (int i = tid; i < SEGT; i += 64){
        float4 vv = *(const float4*)&g_v[(seg*SEGT + i)*512 + b*64 + dq*4];
        *(float4*)&s_v[i*4] = vv;
    }
    __syncthreads();
    int dg = tid >> 4, nq = tid & 15;
    int d = dq*4 + dg;
    float4 acc = make_float4(0.f, 0.f, 0.f, 0.f);
    for (int s = 0; s < seg; s++){
        float4 pv = *(const float4*)&g_P[(s*B_DIM + b)*4096 + d*64 + nq*4];
        acc.x += pv.x; acc.y += pv.y; acc.z += pv.z; acc.w += pv.w;
    }
    const float* kdp = g_kd + seg*SEGT*512 + b*64 + nq*4;
    float* outp = out + (size_t)(seg*SEGT)*32768 + b*4096 + d*64 + nq*4;
    #pragma unroll 8
    for (int t = 0; t < SEGT; t++){
        float4 kd = *(const float4*)(kdp + t*512);
        float vv = s_v[t*4 + dg];
        acc.x = fmaf(vv, kd.x, acc.x);
        acc.y = fmaf(vv, kd.y, acc.y);
        acc.z = fmaf(vv, kd.z, acc.z);
        acc.w = fmaf(vv, kd.w, acc.w);
        *(float4*)(outp + (size_t)t*32768) = acc;
    }
}

// ---------------- launch ----------------
extern "C" void kernel_launch(void* const* d_in, const int* in_sizes, int n_in,
                              void* d_out, int out_size){
    const float* x  = (const float*)d_in[0];
    const float* Wv = (const float*)d_in[1];
    const float* bv = (const float*)d_in[2];
    const float* Wk = (const float*)d_in[3];
    const float* bk = (const float*)d_in[4];
    const float* Wa = (const float*)d_in[5];
    const float* ba = (const float*)d_in[6];
    float* out = (float*)d_out;

    pack_weights<<<(NOUT*INDIM + 255)/256, 256>>>(Wv, bv, Wk, bk, Wa, ba);
    proj_kernel<<<M_TOT/64, 128>>>(x);
    chunk_logsum<<<NCH, 512>>>();
    carry_prefix<<<16, 1024>>>();
    decay_fold<<<NCH, 512>>>();
    dim3 g4(16, B_DIM, NSEG-1);
    seg_partial<<<g4, 64>>>();
    dim3 g5(16, B_DIM, NSEG);
    scan_kernel<<<g5, 64>>>(out);
}